// round 7
// baseline (speedup 1.0000x reference)
#include <cuda_runtime.h>
#include <cuda_bf16.h>
#include <cstdint>

// Problem dims
#define B_  2
#define S_  2048
#define D_  1024
#define H_  16
#define HD_ 64
#define GM  (B_ * S_)   // 4096
#define GN  D_          // 1024
#define GK  D_          // 1024

// ---------------------------------------------------------------------------
// Scratch (__device__ globals; allocation-free rule)
// ---------------------------------------------------------------------------
__device__ __nv_bfloat16 g_x_hi[GM * GK];
__device__ __nv_bfloat16 g_x_lo[GM * GK];
__device__ __nv_bfloat16 g_qh[B_ * H_ * S_ * HD_];   // [B,H,S,HD]
__device__ __nv_bfloat16 g_ql[B_ * H_ * S_ * HD_];
__device__ __nv_bfloat16 g_kh[B_ * H_ * S_ * HD_];
__device__ __nv_bfloat16 g_kl[B_ * H_ * S_ * HD_];
__device__ __nv_bfloat16 g_vh[B_ * H_ * S_ * HD_];
__device__ __nv_bfloat16 g_vl[B_ * H_ * S_ * HD_];
__device__ __nv_bfloat16 g_ctx_hi[GM * GK];          // [B,S,D]
__device__ __nv_bfloat16 g_ctx_lo[GM * GK];
// transposed weights [N, K] K-major
__device__ __nv_bfloat16 g_wqt_hi[GN * GK];
__device__ __nv_bfloat16 g_wqt_lo[GN * GK];
__device__ __nv_bfloat16 g_wkt_hi[GN * GK];
__device__ __nv_bfloat16 g_wkt_lo[GN * GK];
__device__ __nv_bfloat16 g_wvt_hi[GN * GK];
__device__ __nv_bfloat16 g_wvt_lo[GN * GK];
__device__ __nv_bfloat16 g_wot_hi[GN * GK];
__device__ __nv_bfloat16 g_wot_lo[GN * GK];

// ---------------------------------------------------------------------------
// Warp-MMA / async-copy primitives (sm_80+; valid for plain sm_103 target)
// ---------------------------------------------------------------------------
__device__ __forceinline__ uint32_t smem_u32(const void* p) {
    uint32_t a;
    asm("{ .reg .u64 t; cvta.to.shared.u64 t, %1; cvt.u32.u64 %0, t; }"
        : "=r"(a) : "l"(p));
    return a;
}

__device__ __forceinline__ void mma16816(float* c, const uint32_t* a,
                                         uint32_t b0, uint32_t b1) {
    asm volatile(
        "mma.sync.aligned.m16n8k16.row.col.f32.bf16.bf16.f32 "
        "{%0,%1,%2,%3}, {%4,%5,%6,%7}, {%8,%9}, {%0,%1,%2,%3};"
        : "+f"(c[0]), "+f"(c[1]), "+f"(c[2]), "+f"(c[3])
        : "r"(a[0]), "r"(a[1]), "r"(a[2]), "r"(a[3]), "r"(b0), "r"(b1));
}

__device__ __forceinline__ void ldmx4(uint32_t* r, uint32_t addr) {
    asm volatile("ldmatrix.sync.aligned.m8n8.x4.shared.b16 {%0,%1,%2,%3}, [%4];"
        : "=r"(r[0]), "=r"(r[1]), "=r"(r[2]), "=r"(r[3]) : "r"(addr));
}

__device__ __forceinline__ void ldmx4t(uint32_t* r, uint32_t addr) {
    asm volatile("ldmatrix.sync.aligned.m8n8.x4.trans.shared.b16 {%0,%1,%2,%3}, [%4];"
        : "=r"(r[0]), "=r"(r[1]), "=r"(r[2]), "=r"(r[3]) : "r"(addr));
}

__device__ __forceinline__ void cpa16(uint32_t s, const void* g) {
    asm volatile("cp.async.cg.shared.global [%0], [%1], 16;"
                 :: "r"(s), "l"(g) : "memory");
}
#define CP_COMMIT() asm volatile("cp.async.commit_group;" ::: "memory")
#define CP_WAIT(n)  asm volatile("cp.async.wait_group %0;" :: "n"(n) : "memory")

__device__ __forceinline__ unsigned pack_hi(float x, float y) {
    __nv_bfloat162 t = __floats2bfloat162_rn(x, y);
    return *reinterpret_cast<unsigned*>(&t);
}
__device__ __forceinline__ unsigned pack_lo(float x, float y) {
    float xr = x - __bfloat162float(__float2bfloat16(x));
    float yr = y - __bfloat162float(__float2bfloat16(y));
    __nv_bfloat162 t = __floats2bfloat162_rn(xr, yr);
    return *reinterpret_cast<unsigned*>(&t);
}

// ---------------------------------------------------------------------------
// GEMM: C[128,128] tile of A[M,K] @ B[N,K]^T, split-bf16 3-term, fp32 acc.
// 256 threads = 8 warps (2m x 4n); warp tile 64x32; KC=32; 3-stage cp.async.
// MODE 0: A = x, B = Wq/Wk/Wv (blockIdx.z); out -> bf16 hi/lo [B,H,S,HD]
// MODE 1: A = ctx, B = Wo; out -> fp32 [M,N] + bias
// ---------------------------------------------------------------------------
#define GP 40                 // smem pitch in bf16 (80 bytes)
#define GT (128 * GP * 2)     // one tile: 10240 bytes
#define GSTAGE (4 * GT)       // one stage (Ah,Al,Bh,Bl): 40960 bytes
#define SMEM_GEMM (3 * GSTAGE)

__device__ __forceinline__ void gemm_issue(uint32_t sb,
    const char* Ah, const char* Al, const char* Bh, const char* Bl,
    int m0, int n0, int c, int t)
{
    int lrow = t >> 1, lq = (t & 1) * 2;
    size_t goA = (size_t)(m0 + lrow) * (GK * 2) + (size_t)c * 64 + lq * 16;
    size_t goB = (size_t)(n0 + lrow) * (GK * 2) + (size_t)c * 64 + lq * 16;
    uint32_t soff = lrow * (GP * 2) + lq * 16;
    cpa16(sb + soff,               Ah + goA);
    cpa16(sb + soff + 16,          Ah + goA + 16);
    cpa16(sb + GT + soff,          Al + goA);
    cpa16(sb + GT + soff + 16,     Al + goA + 16);
    cpa16(sb + 2 * GT + soff,      Bh + goB);
    cpa16(sb + 2 * GT + soff + 16, Bh + goB + 16);
    cpa16(sb + 3 * GT + soff,      Bl + goB);
    cpa16(sb + 3 * GT + soff + 16, Bl + goB + 16);
}

template <int MODE>
__global__ __launch_bounds__(256, 1)
void mma_gemm_kernel(const float* __restrict__ bias, float* __restrict__ dout)
{
    extern __shared__ char smem[];
    const uint32_t sbase = smem_u32(smem);

    const __nv_bfloat16 *Ah, *Al, *Bh, *Bl;
    __nv_bfloat16 *OutH = nullptr, *OutL = nullptr;
    if (MODE == 0) {
        Ah = g_x_hi; Al = g_x_lo;
        if (blockIdx.z == 0)      { Bh = g_wqt_hi; Bl = g_wqt_lo; OutH = g_qh; OutL = g_ql; }
        else if (blockIdx.z == 1) { Bh = g_wkt_hi; Bl = g_wkt_lo; OutH = g_kh; OutL = g_kl; }
        else                      { Bh = g_wvt_hi; Bl = g_wvt_lo; OutH = g_vh; OutL = g_vl; }
    } else {
        Ah = g_ctx_hi; Al = g_ctx_lo; Bh = g_wot_hi; Bl = g_wot_lo;
    }

    const int m0   = blockIdx.y * 128;
    const int n0   = blockIdx.x * 128;
    const int t    = threadIdx.x;
    const int lane = t & 31;
    const int wid  = t >> 5;
    const int wm   = wid >> 2;     // 0..1
    const int wn   = wid & 3;      // 0..3

    float acc[4][4][4] = {};

    const int NC = GK / 32;        // 32 chunks
    gemm_issue(sbase, (const char*)Ah, (const char*)Al,
               (const char*)Bh, (const char*)Bl, m0, n0, 0, t);
    CP_COMMIT();
    gemm_issue(sbase + GSTAGE, (const char*)Ah, (const char*)Al,
               (const char*)Bh, (const char*)Bl, m0, n0, 1, t);
    CP_COMMIT();

    for (int c = 0; c < NC; c++) {
        // issue chunk c+2 into stage (c+2)%3 (safe: bottom barrier of c-1 passed)
        if (c + 2 < NC) {
            gemm_issue(sbase + ((c + 2) % 3) * GSTAGE,
                       (const char*)Ah, (const char*)Al,
                       (const char*)Bh, (const char*)Bl, m0, n0, c + 2, t);
            CP_COMMIT();
            CP_WAIT(2);            // chunk c's group complete
        } else if (c + 1 < NC) {
            CP_WAIT(1);
        } else {
            CP_WAIT(0);
        }
        __syncthreads();

        const uint32_t sb  = sbase + (c % 3) * GSTAGE;
        const uint32_t uAh = sb,          uAl = sb + GT;
        const uint32_t uBh = sb + 2 * GT, uBl = sb + 3 * GT;

        #pragma unroll
        for (int ks = 0; ks < 2; ks++) {
            uint32_t a_h[4][4], a_l[4][4];
            int abyte = (wm * 64 + (lane & 15)) * (GP * 2) + ks * 32 + (lane >> 4) * 16;
            #pragma unroll
            for (int mt = 0; mt < 4; mt++) {
                ldmx4(a_h[mt], uAh + abyte + mt * 16 * (GP * 2));
                ldmx4(a_l[mt], uAl + abyte + mt * 16 * (GP * 2));
            }
            #pragma unroll
            for (int j = 0; j < 2; j++) {
                uint32_t b_h[4], b_l[4];
                int bbyte = (wn * 32 + j * 16 + ((lane >> 4) << 3) + (lane & 7)) * (GP * 2)
                          + ks * 32 + ((lane >> 3) & 1) * 16;
                ldmx4(b_h, uBh + bbyte);
                ldmx4(b_l, uBl + bbyte);
                #pragma unroll
                for (int mt = 0; mt < 4; mt++) {
                    // interleave the two accumulator chains
                    mma16816(acc[mt][2 * j],     a_h[mt], b_h[0], b_h[1]);
                    mma16816(acc[mt][2 * j + 1], a_h[mt], b_h[2], b_h[3]);
                    mma16816(acc[mt][2 * j],     a_h[mt], b_l[0], b_l[1]);
                    mma16816(acc[mt][2 * j + 1], a_h[mt], b_l[2], b_l[3]);
                    mma16816(acc[mt][2 * j],     a_l[mt], b_h[0], b_h[1]);
                    mma16816(acc[mt][2 * j + 1], a_l[mt], b_h[2], b_h[3]);
                }
            }
        }
        __syncthreads();
    }

    // Epilogue
    #pragma unroll
    for (int mt = 0; mt < 4; mt++) {
        int mA = m0 + wm * 64 + mt * 16 + (lane >> 2);
        int mB = mA + 8;
        #pragma unroll
        for (int nt = 0; nt < 4; nt++) {
            int n = n0 + wn * 32 + nt * 8 + (lane & 3) * 2;
            float c0 = acc[mt][nt][0], c1 = acc[mt][nt][1];
            float c2 = acc[mt][nt][2], c3 = acc[mt][nt][3];
            if (MODE == 0) {
                int h = n >> 6, hd = n & 63;
                {
                    int b = mA >> 11, s = mA & (S_ - 1);
                    size_t o = ((size_t)((b * H_ + h) * S_) + s) * HD_ + hd;
                    *(unsigned*)&OutH[o] = pack_hi(c0, c1);
                    *(unsigned*)&OutL[o] = pack_lo(c0, c1);
                }
                {
                    int b = mB >> 11, s = mB & (S_ - 1);
                    size_t o = ((size_t)((b * H_ + h) * S_) + s) * HD_ + hd;
                    *(unsigned*)&OutH[o] = pack_hi(c2, c3);
                    *(unsigned*)&OutL[o] = pack_lo(c2, c3);
                }
            } else {
                float b0 = bias[n], b1 = bias[n + 1];
                *(float2*)&dout[(size_t)mA * GN + n] = make_float2(c0 + b0, c1 + b1);
                *(float2*)&dout[(size_t)mB * GN + n] = make_float2(c2 + b0, c3 + b1);
            }
        }
    }
}

// ---------------------------------------------------------------------------
// Flash attention with warp MMA, causal, split-bf16 3-term, 2-stage cp.async.
// grid (S/64, B*H), 128 threads = 4 warps; warp owns 16 query rows.
// ---------------------------------------------------------------------------
#define AP 72                 // smem pitch in bf16 (144 bytes)
#define AT (64 * AP * 2)      // one tile: 9216 bytes
#define ASTAGE (4 * AT)       // Kh,Kl,Vh,Vl: 36864 bytes
#define SMEM_ATTN (2 * ASTAGE)

__device__ __forceinline__ void attn_issue_kv(uint32_t sb,
    const __nv_bfloat16* Kh, const __nv_bfloat16* Kl,
    const __nv_bfloat16* Vh, const __nv_bfloat16* Vl, int kb, int t)
{
    const uint4* gkh = (const uint4*)(Kh + (size_t)kb * 64 * HD_);
    const uint4* gkl = (const uint4*)(Kl + (size_t)kb * 64 * HD_);
    const uint4* gvh = (const uint4*)(Vh + (size_t)kb * 64 * HD_);
    const uint4* gvl = (const uint4*)(Vl + (size_t)kb * 64 * HD_);
    #pragma unroll
    for (int p = 0; p < 4; p++) {
        int idx = t + p * 128;
        int row = idx >> 3, q = idx & 7;
        uint32_t soff = row * (AP * 2) + q * 16;
        cpa16(sb + soff,          gkh + idx);
        cpa16(sb + AT + soff,     gkl + idx);
        cpa16(sb + 2 * AT + soff, gvh + idx);
        cpa16(sb + 3 * AT + soff, gvl + idx);
    }
}

__global__ __launch_bounds__(128, 3)
void attn_mma_kernel()
{
    extern __shared__ char smem[];
    const uint32_t sbase = smem_u32(smem);

    const int qb   = blockIdx.x;
    const int bh   = blockIdx.y;
    const int t    = threadIdx.x;
    const int lane = t & 31;
    const int wid  = t >> 5;

    const size_t head_off = (size_t)bh * S_ * HD_;
    const __nv_bfloat16* Qh = g_qh + head_off + (size_t)qb * 64 * HD_;
    const __nv_bfloat16* Ql = g_ql + head_off + (size_t)qb * 64 * HD_;
    const __nv_bfloat16* Kh = g_kh + head_off;
    const __nv_bfloat16* Kl = g_kl + head_off;
    const __nv_bfloat16* Vh = g_vh + head_off;
    const __nv_bfloat16* Vl = g_vl + head_off;

    // ---- stage Q into stage-1 K buffers via cp.async (group 0) ----
    {
        uint32_t qsb = sbase + ASTAGE;
        #pragma unroll
        for (int p = 0; p < 4; p++) {
            int idx = t + p * 128;
            int row = idx >> 3, q = idx & 7;
            uint32_t soff = row * (AP * 2) + q * 16;
            cpa16(qsb + soff,      ((const uint4*)Qh) + idx);
            cpa16(qsb + AT + soff, ((const uint4*)Ql) + idx);
        }
        CP_COMMIT();
    }
    // ---- kb=0 K/V into stage 0 (group 1) ----
    attn_issue_kv(sbase, Kh, Kl, Vh, Vl, 0, t);
    CP_COMMIT();

    CP_WAIT(1);           // Q group done; kb0 may still be in flight
    __syncthreads();

    uint32_t aq_h[4][4], aq_l[4][4];
    {
        uint32_t uQh = sbase + ASTAGE, uQl = sbase + ASTAGE + AT;
        int qbyte = (wid * 16 + (lane & 15)) * (AP * 2) + (lane >> 4) * 16;
        #pragma unroll
        for (int kc = 0; kc < 4; kc++) {
            ldmx4(aq_h[kc], uQh + qbyte + kc * 32);
            ldmx4(aq_l[kc], uQl + qbyte + kc * 32);
        }
    }
    __syncthreads();      // all warps have Q frags; stage-1 reusable

    float oAcc[8][4] = {};
    float m0r = -1e30f, m1r = -1e30f;
    float l0 = 0.0f, l1 = 0.0f;

    for (int kb = 0; kb <= qb; kb++) {
        if (kb < qb) {
            attn_issue_kv(sbase + ((kb + 1) & 1) * ASTAGE, Kh, Kl, Vh, Vl, kb + 1, t);
            CP_COMMIT();
            CP_WAIT(1);
        } else {
            CP_WAIT(0);
        }
        __syncthreads();

        const uint32_t sb  = sbase + (kb & 1) * ASTAGE;
        const uint32_t uKh = sb,          uKl = sb + AT;
        const uint32_t uVh = sb + 2 * AT, uVl = sb + 3 * AT;

        // ---- S = Q K^T (3-term, interleaved chains) ----
        float sc[8][4] = {};
        #pragma unroll
        for (int kc = 0; kc < 4; kc++) {
            #pragma unroll
            for (int j = 0; j < 4; j++) {
                uint32_t b_h[4], b_l[4];
                int bbyte = (j * 16 + ((lane >> 4) << 3) + (lane & 7)) * (AP * 2)
                          + kc * 32 + ((lane >> 3) & 1) * 16;
                ldmx4(b_h, uKh + bbyte);
                ldmx4(b_l, uKl + bbyte);
                mma16816(sc[2 * j],     aq_h[kc], b_h[0], b_h[1]);
                mma16816(sc[2 * j + 1], aq_h[kc], b_h[2], b_h[3]);
                mma16816(sc[2 * j],     aq_h[kc], b_l[0], b_l[1]);
                mma16816(sc[2 * j + 1], aq_h[kc], b_l[2], b_l[3]);
                mma16816(sc[2 * j],     aq_l[kc], b_h[0], b_h[1]);
                mma16816(sc[2 * j + 1], aq_l[kc], b_h[2], b_h[3]);
            }
        }

        // ---- scale + causal mask (diagonal block only) ----
        #pragma unroll
        for (int nt = 0; nt < 8; nt++) {
            #pragma unroll
            for (int i = 0; i < 4; i++) sc[nt][i] *= 0.125f;
        }
        if (kb == qb) {
            int r0l = wid * 16 + (lane >> 2);
            #pragma unroll
            for (int nt = 0; nt < 8; nt++) {
                int col = nt * 8 + (lane & 3) * 2;
                if (col > r0l)         sc[nt][0] = -1e30f;
                if (col + 1 > r0l)     sc[nt][1] = -1e30f;
                if (col > r0l + 8)     sc[nt][2] = -1e30f;
                if (col + 1 > r0l + 8) sc[nt][3] = -1e30f;
            }
        }

        // ---- online softmax ----
        float mx0 = -1e30f, mx1 = -1e30f;
        #pragma unroll
        for (int nt = 0; nt < 8; nt++) {
            mx0 = fmaxf(mx0, fmaxf(sc[nt][0], sc[nt][1]));
            mx1 = fmaxf(mx1, fmaxf(sc[nt][2], sc[nt][3]));
        }
        mx0 = fmaxf(mx0, __shfl_xor_sync(0xffffffffu, mx0, 1));
        mx0 = fmaxf(mx0, __shfl_xor_sync(0xffffffffu, mx0, 2));
        mx1 = fmaxf(mx1, __shfl_xor_sync(0xffffffffu, mx1, 1));
        mx1 = fmaxf(mx1, __shfl_xor_sync(0xffffffffu, mx1, 2));

        float mn0 = fmaxf(m0r, mx0), mn1 = fmaxf(m1r, mx1);
        float cr0 = __expf(m0r - mn0), cr1 = __expf(m1r - mn1);

        float sum0 = 0.0f, sum1 = 0.0f;
        #pragma unroll
        for (int nt = 0; nt < 8; nt++) {
            float p0 = __expf(sc[nt][0] - mn0);
            float p1 = __expf(sc[nt][1] - mn0);
            float p2 = __expf(sc[nt][2] - mn1);
            float p3 = __expf(sc[nt][3] - mn1);
            sc[nt][0] = p0; sc[nt][1] = p1; sc[nt][2] = p2; sc[nt][3] = p3;
            sum0 += p0 + p1;
            sum1 += p2 + p3;
        }
        sum0 += __shfl_xor_sync(0xffffffffu, sum0, 1);
        sum0 += __shfl_xor_sync(0xffffffffu, sum0, 2);
        sum1 += __shfl_xor_sync(0xffffffffu, sum1, 1);
        sum1 += __shfl_xor_sync(0xffffffffu, sum1, 2);

        l0 = l0 * cr0 + sum0;  m0r = mn0;
        l1 = l1 * cr1 + sum1;  m1r = mn1;

        #pragma unroll
        for (int nt = 0; nt < 8; nt++) {
            oAcc[nt][0] *= cr0; oAcc[nt][1] *= cr0;
            oAcc[nt][2] *= cr1; oAcc[nt][3] *= cr1;
        }

        // ---- O += P V (3-term, interleaved chains; V frags via ldmatrix.trans) ----
        #pragma unroll
        for (int kc = 0; kc < 4; kc++) {
            uint32_t pa_h[4], pa_l[4];
            pa_h[0] = pack_hi(sc[2 * kc][0],     sc[2 * kc][1]);
            pa_h[1] = pack_hi(sc[2 * kc][2],     sc[2 * kc][3]);
            pa_h[2] = pack_hi(sc[2 * kc + 1][0], sc[2 * kc + 1][1]);
            pa_h[3] = pack_hi(sc[2 * kc + 1][2], sc[2 * kc + 1][3]);
            pa_l[0] = pack_lo(sc[2 * kc][0],     sc[2 * kc][1]);
            pa_l[1] = pack_lo(sc[2 * kc][2],     sc[2 * kc][3]);
            pa_l[2] = pack_lo(sc[2 * kc + 1][0], sc[2 * kc + 1][1]);
            pa_l[3] = pack_lo(sc[2 * kc + 1][2], sc[2 * kc + 1][3]);
            #pragma unroll
            for (int j = 0; j < 4; j++) {
                uint32_t v_h[4], v_l[4];
                int key   = kc * 16 + ((lane >> 3) & 1) * 8 + (lane & 7);
                int hd    = j * 16 + (lane >> 4) * 8;
                int vbyte = key * (AP * 2) + hd * 2;
                ldmx4t(v_h, uVh + vbyte);
                ldmx4t(v_l, uVl + vbyte);
                mma16816(oAcc[2 * j],     pa_h, v_h[0], v_h[1]);
                mma16816(oAcc[2 * j + 1], pa_h, v_h[2], v_h[3]);
                mma16816(oAcc[2 * j],     pa_h, v_l[0], v_l[1]);
                mma16816(oAcc[2 * j + 1], pa_h, v_l[2], v_l[3]);
                mma16816(oAcc[2 * j],     pa_l, v_h[0], v_h[1]);
                mma16816(oAcc[2 * j + 1], pa_l, v_h[2], v_h[3]);
            }
        }
        __syncthreads();
    }

    // ---- finalize: ctx hi/lo bf16 [B,S,D] ----
    const float inv0 = 1.0f / l0, inv1 = 1.0f / l1;
    const int b = bh >> 4, h = bh & 15;
    const int r0 = qb * 64 + wid * 16 + (lane >> 2);
    const int r1 = r0 + 8;
    #pragma unroll
    for (int nt = 0; nt < 8; nt++) {
        int hd = nt * 8 + (lane & 3) * 2;
        float v0 = oAcc[nt][0] * inv0, v1 = oAcc[nt][1] * inv0;
        float v2 = oAcc[nt][2] * inv1, v3 = oAcc[nt][3] * inv1;
        size_t o0 = ((size_t)(b * S_ + r0)) * D_ + h * HD_ + hd;
        size_t o1 = ((size_t)(b * S_ + r1)) * D_ + h * HD_ + hd;
        *(unsigned*)&g_ctx_hi[o0] = pack_hi(v0, v1);
        *(unsigned*)&g_ctx_lo[o0] = pack_lo(v0, v1);
        *(unsigned*)&g_ctx_hi[o1] = pack_hi(v2, v3);
        *(unsigned*)&g_ctx_lo[o1] = pack_lo(v2, v3);
    }
}

// ---------------------------------------------------------------------------
// fp32 -> (bf16 hi, bf16 lo) split of x (writes device globals directly)
// ---------------------------------------------------------------------------
__global__ void split_x_kernel(const float4* __restrict__ src)
{
    int i = blockIdx.x * blockDim.x + threadIdx.x;
    if (i >= GM * GK / 4) return;
    float4 v = src[i];
    __nv_bfloat16 hx = __float2bfloat16(v.x), hy = __float2bfloat16(v.y);
    __nv_bfloat16 hz = __float2bfloat16(v.z), hw = __float2bfloat16(v.w);
    __nv_bfloat16 lx = __float2bfloat16(v.x - __bfloat162float(hx));
    __nv_bfloat16 ly = __float2bfloat16(v.y - __bfloat162float(hy));
    __nv_bfloat16 lz = __float2bfloat16(v.z - __bfloat162float(hz));
    __nv_bfloat16 lw = __float2bfloat16(v.w - __bfloat162float(hw));
    ((__nv_bfloat162*)g_x_hi)[i * 2]     = __nv_bfloat162(hx, hy);
    ((__nv_bfloat162*)g_x_hi)[i * 2 + 1] = __nv_bfloat162(hz, hw);
    ((__nv_bfloat162*)g_x_lo)[i * 2]     = __nv_bfloat162(lx, ly);
    ((__nv_bfloat162*)g_x_lo)[i * 2 + 1] = __nv_bfloat162(lz, lw);
}

// ---------------------------------------------------------------------------
// Batched: W [K,N] fp32 -> Wt [N,K] bf16 hi/lo for all 4 weights (blockIdx.z)
// ---------------------------------------------------------------------------
__global__ void transpose_split4_kernel(const float* __restrict__ W0,
                                        const float* __restrict__ W1,
                                        const float* __restrict__ W2,
                                        const float* __restrict__ W3)
{
    __shared__ float tile[32][33];
    const float* W;
    __nv_bfloat16 *hi, *lo;
    switch (blockIdx.z) {
        case 0:  W = W0; hi = g_wqt_hi; lo = g_wqt_lo; break;
        case 1:  W = W1; hi = g_wkt_hi; lo = g_wkt_lo; break;
        case 2:  W = W2; hi = g_wvt_hi; lo = g_wvt_lo; break;
        default: W = W3; hi = g_wot_hi; lo = g_wot_lo; break;
    }
    const int tx = threadIdx.x, ty = threadIdx.y;
    const int k0 = blockIdx.y * 32;
    const int n0 = blockIdx.x * 32;
    #pragma unroll
    for (int j = 0; j < 4; j++)
        tile[ty + j * 8][tx] = W[(size_t)(k0 + ty + j * 8) * GN + n0 + tx];
    __syncthreads();
    #pragma unroll
    for (int j = 0; j < 4; j++) {
        int n = n0 + ty + j * 8;
        int k = k0 + tx;
        float v = tile[tx][ty + j * 8];
        __nv_bfloat16 hv = __float2bfloat16(v);
        hi[(size_t)n * GK + k] = hv;
        lo[(size_t)n * GK + k] = __float2bfloat16(v - __bfloat162float(hv));
    }
}

// ---------------------------------------------------------------------------
extern "C" void kernel_launch(void* const* d_in, const int* in_sizes, int n_in,
                              void* d_out, int out_size)
{
    const float* x  = (const float*)d_in[0];
    const float* Wq = (const float*)d_in[1];
    const float* Wk = (const float*)d_in[2];
    const float* Wv = (const float*)d_in[3];
    const float* Wo = (const float*)d_in[4];
    const float* bo = (const float*)d_in[5];
    float*       out = (float*)d_out;

    cudaFuncSetAttribute(mma_gemm_kernel<0>,
                         cudaFuncAttributeMaxDynamicSharedMemorySize, SMEM_GEMM);
    cudaFuncSetAttribute(mma_gemm_kernel<1>,
                         cudaFuncAttributeMaxDynamicSharedMemorySize, SMEM_GEMM);
    cudaFuncSetAttribute(attn_mma_kernel,
                         cudaFuncAttributeMaxDynamicSharedMemorySize, SMEM_ATTN);

    // 1) prep: split x, transpose+split all 4 weights (batched)
    split_x_kernel<<<(GM * GK / 4 + 255) / 256, 256>>>((const float4*)x);
    transpose_split4_kernel<<<dim3(GN / 32, GK / 32, 4), dim3(32, 8)>>>(Wq, Wk, Wv, Wo);

    // 2) QKV projections (warp MMA, 3-stage cp.async) -> bf16 hi/lo [B,H,S,HD]
    mma_gemm_kernel<0><<<dim3(GN / 128, GM / 128, 3), 256, SMEM_GEMM>>>(nullptr, nullptr);

    // 3) attention (warp MMA flash, cp.async, occ=3) -> ctx hi/lo [B,S,D]
    attn_mma_kernel<<<dim3(S_ / 64, B_ * H_), 128, SMEM_ATTN>>>();

    // 4) output projection + bias (warp MMA) -> fp32 out
    mma_gemm_kernel<1><<<dim3(GN / 128, GM / 128, 1), 256, SMEM_GEMM>>>(bo, out);
}

// round 8
// speedup vs baseline: 1.1055x; 1.1055x over previous
#include <cuda_runtime.h>
#include <cuda_bf16.h>
#include <cstdint>

// Problem dims
#define B_  2
#define S_  2048
#define D_  1024
#define H_  16
#define HD_ 64
#define GM  (B_ * S_)   // 4096
#define GN  D_          // 1024
#define GK  D_          // 1024

// ---------------------------------------------------------------------------
// Scratch (__device__ globals; allocation-free rule)
// ---------------------------------------------------------------------------
__device__ __nv_bfloat16 g_x_hi[GM * GK];
__device__ __nv_bfloat16 g_x_lo[GM * GK];
__device__ __nv_bfloat16 g_qh[B_ * H_ * S_ * HD_];   // [B,H,S,HD]
__device__ __nv_bfloat16 g_ql[B_ * H_ * S_ * HD_];
__device__ __nv_bfloat16 g_kh[B_ * H_ * S_ * HD_];
__device__ __nv_bfloat16 g_kl[B_ * H_ * S_ * HD_];
__device__ __nv_bfloat16 g_vh[B_ * H_ * S_ * HD_];
__device__ __nv_bfloat16 g_vl[B_ * H_ * S_ * HD_];
__device__ __nv_bfloat16 g_ctx_hi[GM * GK];          // [B,S,D]
__device__ __nv_bfloat16 g_ctx_lo[GM * GK];
// transposed weights [N, K] K-major
__device__ __nv_bfloat16 g_wqt_hi[GN * GK];
__device__ __nv_bfloat16 g_wqt_lo[GN * GK];
__device__ __nv_bfloat16 g_wkt_hi[GN * GK];
__device__ __nv_bfloat16 g_wkt_lo[GN * GK];
__device__ __nv_bfloat16 g_wvt_hi[GN * GK];
__device__ __nv_bfloat16 g_wvt_lo[GN * GK];
__device__ __nv_bfloat16 g_wot_hi[GN * GK];
__device__ __nv_bfloat16 g_wot_lo[GN * GK];

// ---------------------------------------------------------------------------
// Warp-MMA / async-copy primitives (sm_80+; valid for plain sm_103 target)
// ---------------------------------------------------------------------------
__device__ __forceinline__ uint32_t smem_u32(const void* p) {
    uint32_t a;
    asm("{ .reg .u64 t; cvta.to.shared.u64 t, %1; cvt.u32.u64 %0, t; }"
        : "=r"(a) : "l"(p));
    return a;
}

__device__ __forceinline__ void mma16816(float* c, const uint32_t* a,
                                         uint32_t b0, uint32_t b1) {
    asm volatile(
        "mma.sync.aligned.m16n8k16.row.col.f32.bf16.bf16.f32 "
        "{%0,%1,%2,%3}, {%4,%5,%6,%7}, {%8,%9}, {%0,%1,%2,%3};"
        : "+f"(c[0]), "+f"(c[1]), "+f"(c[2]), "+f"(c[3])
        : "r"(a[0]), "r"(a[1]), "r"(a[2]), "r"(a[3]), "r"(b0), "r"(b1));
}

__device__ __forceinline__ void ldmx4(uint32_t* r, uint32_t addr) {
    asm volatile("ldmatrix.sync.aligned.m8n8.x4.shared.b16 {%0,%1,%2,%3}, [%4];"
        : "=r"(r[0]), "=r"(r[1]), "=r"(r[2]), "=r"(r[3]) : "r"(addr));
}

__device__ __forceinline__ void ldmx4t(uint32_t* r, uint32_t addr) {
    asm volatile("ldmatrix.sync.aligned.m8n8.x4.trans.shared.b16 {%0,%1,%2,%3}, [%4];"
        : "=r"(r[0]), "=r"(r[1]), "=r"(r[2]), "=r"(r[3]) : "r"(addr));
}

__device__ __forceinline__ void cpa16(uint32_t s, const void* g) {
    asm volatile("cp.async.cg.shared.global [%0], [%1], 16;"
                 :: "r"(s), "l"(g) : "memory");
}
#define CP_COMMIT() asm volatile("cp.async.commit_group;" ::: "memory")
#define CP_WAIT(n)  asm volatile("cp.async.wait_group %0;" :: "n"(n) : "memory")

__device__ __forceinline__ unsigned pack_hi(float x, float y) {
    __nv_bfloat162 t = __floats2bfloat162_rn(x, y);
    return *reinterpret_cast<unsigned*>(&t);
}
__device__ __forceinline__ unsigned pack_lo(float x, float y) {
    float xr = x - __bfloat162float(__float2bfloat16(x));
    float yr = y - __bfloat162float(__float2bfloat16(y));
    __nv_bfloat162 t = __floats2bfloat162_rn(xr, yr);
    return *reinterpret_cast<unsigned*>(&t);
}

// ---------------------------------------------------------------------------
// GEMM: C[128,128] tile of A[M,K] @ B[N,K]^T, split-bf16 3-term, fp32 acc.
// 256 threads = 8 warps (2m x 4n); warp tile 64x32; KC=32; 2-stage cp.async.
// __launch_bounds__(256, 2): 2 CTAs/SM (160KB smem, regs capped at 128).
// MODE 0: A = x, B = Wq/Wk/Wv (blockIdx.z); out -> bf16 hi/lo [B,H,S,HD]
// MODE 1: A = ctx, B = Wo; out -> fp32 [M,N] + bias
// ---------------------------------------------------------------------------
#define GP 40                 // smem pitch in bf16 (80 bytes)
#define GT (128 * GP * 2)     // one tile: 10240 bytes
#define GSTAGE (4 * GT)       // one stage (Ah,Al,Bh,Bl): 40960 bytes
#define SMEM_GEMM (2 * GSTAGE)

__device__ __forceinline__ void gemm_issue(uint32_t sb,
    const char* Ah, const char* Al, const char* Bh, const char* Bl,
    int m0, int n0, int c, int t)
{
    int lrow = t >> 1, lq = (t & 1) * 2;
    size_t goA = (size_t)(m0 + lrow) * (GK * 2) + (size_t)c * 64 + lq * 16;
    size_t goB = (size_t)(n0 + lrow) * (GK * 2) + (size_t)c * 64 + lq * 16;
    uint32_t soff = lrow * (GP * 2) + lq * 16;
    cpa16(sb + soff,               Ah + goA);
    cpa16(sb + soff + 16,          Ah + goA + 16);
    cpa16(sb + GT + soff,          Al + goA);
    cpa16(sb + GT + soff + 16,     Al + goA + 16);
    cpa16(sb + 2 * GT + soff,      Bh + goB);
    cpa16(sb + 2 * GT + soff + 16, Bh + goB + 16);
    cpa16(sb + 3 * GT + soff,      Bl + goB);
    cpa16(sb + 3 * GT + soff + 16, Bl + goB + 16);
}

template <int MODE>
__global__ __launch_bounds__(256, 2)
void mma_gemm_kernel(const float* __restrict__ bias, float* __restrict__ dout)
{
    extern __shared__ char smem[];
    const uint32_t sbase = smem_u32(smem);

    const __nv_bfloat16 *Ah, *Al, *Bh, *Bl;
    __nv_bfloat16 *OutH = nullptr, *OutL = nullptr;
    if (MODE == 0) {
        Ah = g_x_hi; Al = g_x_lo;
        if (blockIdx.z == 0)      { Bh = g_wqt_hi; Bl = g_wqt_lo; OutH = g_qh; OutL = g_ql; }
        else if (blockIdx.z == 1) { Bh = g_wkt_hi; Bl = g_wkt_lo; OutH = g_kh; OutL = g_kl; }
        else                      { Bh = g_wvt_hi; Bl = g_wvt_lo; OutH = g_vh; OutL = g_vl; }
    } else {
        Ah = g_ctx_hi; Al = g_ctx_lo; Bh = g_wot_hi; Bl = g_wot_lo;
    }

    const int m0   = blockIdx.y * 128;
    const int n0   = blockIdx.x * 128;
    const int t    = threadIdx.x;
    const int lane = t & 31;
    const int wid  = t >> 5;
    const int wm   = wid >> 2;     // 0..1
    const int wn   = wid & 3;      // 0..3

    float acc[4][4][4] = {};

    const int NC = GK / 32;
    gemm_issue(sbase, (const char*)Ah, (const char*)Al,
               (const char*)Bh, (const char*)Bl, m0, n0, 0, t);
    CP_COMMIT();

    for (int c = 0; c < NC; c++) {
        if (c + 1 < NC) {
            gemm_issue(sbase + ((c + 1) & 1) * GSTAGE,
                       (const char*)Ah, (const char*)Al,
                       (const char*)Bh, (const char*)Bl, m0, n0, c + 1, t);
            CP_COMMIT();
            CP_WAIT(1);
        } else {
            CP_WAIT(0);
        }
        __syncthreads();

        const uint32_t sb  = sbase + (c & 1) * GSTAGE;
        const uint32_t uAh = sb,          uAl = sb + GT;
        const uint32_t uBh = sb + 2 * GT, uBl = sb + 3 * GT;

        #pragma unroll
        for (int ks = 0; ks < 2; ks++) {
            uint32_t a_h[4][4], a_l[4][4];
            int abyte = (wm * 64 + (lane & 15)) * (GP * 2) + ks * 32 + (lane >> 4) * 16;
            #pragma unroll
            for (int mt = 0; mt < 4; mt++) {
                ldmx4(a_h[mt], uAh + abyte + mt * 16 * (GP * 2));
                ldmx4(a_l[mt], uAl + abyte + mt * 16 * (GP * 2));
            }
            #pragma unroll
            for (int j = 0; j < 2; j++) {
                uint32_t b_h[4], b_l[4];
                int bbyte = (wn * 32 + j * 16 + ((lane >> 4) << 3) + (lane & 7)) * (GP * 2)
                          + ks * 32 + ((lane >> 3) & 1) * 16;
                ldmx4(b_h, uBh + bbyte);
                ldmx4(b_l, uBl + bbyte);
                #pragma unroll
                for (int mt = 0; mt < 4; mt++) {
                    mma16816(acc[mt][2 * j],     a_h[mt], b_h[0], b_h[1]);
                    mma16816(acc[mt][2 * j + 1], a_h[mt], b_h[2], b_h[3]);
                    mma16816(acc[mt][2 * j],     a_h[mt], b_l[0], b_l[1]);
                    mma16816(acc[mt][2 * j + 1], a_h[mt], b_l[2], b_l[3]);
                    mma16816(acc[mt][2 * j],     a_l[mt], b_h[0], b_h[1]);
                    mma16816(acc[mt][2 * j + 1], a_l[mt], b_h[2], b_h[3]);
                }
            }
        }
        __syncthreads();
    }

    // Epilogue
    #pragma unroll
    for (int mt = 0; mt < 4; mt++) {
        int mA = m0 + wm * 64 + mt * 16 + (lane >> 2);
        int mB = mA + 8;
        #pragma unroll
        for (int nt = 0; nt < 4; nt++) {
            int n = n0 + wn * 32 + nt * 8 + (lane & 3) * 2;
            float c0 = acc[mt][nt][0], c1 = acc[mt][nt][1];
            float c2 = acc[mt][nt][2], c3 = acc[mt][nt][3];
            if (MODE == 0) {
                int h = n >> 6, hd = n & 63;
                {
                    int b = mA >> 11, s = mA & (S_ - 1);
                    size_t o = ((size_t)((b * H_ + h) * S_) + s) * HD_ + hd;
                    *(unsigned*)&OutH[o] = pack_hi(c0, c1);
                    *(unsigned*)&OutL[o] = pack_lo(c0, c1);
                }
                {
                    int b = mB >> 11, s = mB & (S_ - 1);
                    size_t o = ((size_t)((b * H_ + h) * S_) + s) * HD_ + hd;
                    *(unsigned*)&OutH[o] = pack_hi(c2, c3);
                    *(unsigned*)&OutL[o] = pack_lo(c2, c3);
                }
            } else {
                float b0 = bias[n], b1 = bias[n + 1];
                *(float2*)&dout[(size_t)mA * GN + n] = make_float2(c0 + b0, c1 + b1);
                *(float2*)&dout[(size_t)mB * GN + n] = make_float2(c2 + b0, c3 + b1);
            }
        }
    }
}

// ---------------------------------------------------------------------------
// Flash attention with warp MMA, causal, split-bf16 3-term, 2-stage cp.async.
// grid (S/64, B*H), 128 threads = 4 warps; warp owns 16 query rows.
// __launch_bounds__(128, 2): no register cap pain (R5 sweet spot).
// ---------------------------------------------------------------------------
#define AP 72                 // smem pitch in bf16 (144 bytes)
#define AT (64 * AP * 2)      // one tile: 9216 bytes
#define ASTAGE (4 * AT)       // Kh,Kl,Vh,Vl: 36864 bytes
#define SMEM_ATTN (2 * ASTAGE)

__device__ __forceinline__ void attn_issue_kv(uint32_t sb,
    const __nv_bfloat16* Kh, const __nv_bfloat16* Kl,
    const __nv_bfloat16* Vh, const __nv_bfloat16* Vl, int kb, int t)
{
    const uint4* gkh = (const uint4*)(Kh + (size_t)kb * 64 * HD_);
    const uint4* gkl = (const uint4*)(Kl + (size_t)kb * 64 * HD_);
    const uint4* gvh = (const uint4*)(Vh + (size_t)kb * 64 * HD_);
    const uint4* gvl = (const uint4*)(Vl + (size_t)kb * 64 * HD_);
    #pragma unroll
    for (int p = 0; p < 4; p++) {
        int idx = t + p * 128;
        int row = idx >> 3, q = idx & 7;
        uint32_t soff = row * (AP * 2) + q * 16;
        cpa16(sb + soff,          gkh + idx);
        cpa16(sb + AT + soff,     gkl + idx);
        cpa16(sb + 2 * AT + soff, gvh + idx);
        cpa16(sb + 3 * AT + soff, gvl + idx);
    }
}

__global__ __launch_bounds__(128, 2)
void attn_mma_kernel()
{
    extern __shared__ char smem[];
    const uint32_t sbase = smem_u32(smem);

    const int qb   = blockIdx.x;
    const int bh   = blockIdx.y;
    const int t    = threadIdx.x;
    const int lane = t & 31;
    const int wid  = t >> 5;

    const size_t head_off = (size_t)bh * S_ * HD_;
    const __nv_bfloat16* Qh = g_qh + head_off + (size_t)qb * 64 * HD_;
    const __nv_bfloat16* Ql = g_ql + head_off + (size_t)qb * 64 * HD_;
    const __nv_bfloat16* Kh = g_kh + head_off;
    const __nv_bfloat16* Kl = g_kl + head_off;
    const __nv_bfloat16* Vh = g_vh + head_off;
    const __nv_bfloat16* Vl = g_vl + head_off;

    // ---- stage Q into stage-1 K buffers via cp.async (group 0) ----
    {
        uint32_t qsb = sbase + ASTAGE;
        #pragma unroll
        for (int p = 0; p < 4; p++) {
            int idx = t + p * 128;
            int row = idx >> 3, q = idx & 7;
            uint32_t soff = row * (AP * 2) + q * 16;
            cpa16(qsb + soff,      ((const uint4*)Qh) + idx);
            cpa16(qsb + AT + soff, ((const uint4*)Ql) + idx);
        }
        CP_COMMIT();
    }
    // ---- kb=0 K/V into stage 0 (group 1) ----
    attn_issue_kv(sbase, Kh, Kl, Vh, Vl, 0, t);
    CP_COMMIT();

    CP_WAIT(1);           // Q group done; kb0 may still be in flight
    __syncthreads();

    uint32_t aq_h[4][4], aq_l[4][4];
    {
        uint32_t uQh = sbase + ASTAGE, uQl = sbase + ASTAGE + AT;
        int qbyte = (wid * 16 + (lane & 15)) * (AP * 2) + (lane >> 4) * 16;
        #pragma unroll
        for (int kc = 0; kc < 4; kc++) {
            ldmx4(aq_h[kc], uQh + qbyte + kc * 32);
            ldmx4(aq_l[kc], uQl + qbyte + kc * 32);
        }
    }
    __syncthreads();      // all warps have Q frags; stage-1 reusable

    float oAcc[8][4] = {};
    float m0r = -1e30f, m1r = -1e30f;
    float l0 = 0.0f, l1 = 0.0f;

    for (int kb = 0; kb <= qb; kb++) {
        if (kb < qb) {
            attn_issue_kv(sbase + ((kb + 1) & 1) * ASTAGE, Kh, Kl, Vh, Vl, kb + 1, t);
            CP_COMMIT();
            CP_WAIT(1);
        } else {
            CP_WAIT(0);
        }
        __syncthreads();

        const uint32_t sb  = sbase + (kb & 1) * ASTAGE;
        const uint32_t uKh = sb,          uKl = sb + AT;
        const uint32_t uVh = sb + 2 * AT, uVl = sb + 3 * AT;

        // ---- S = Q K^T (3-term, interleaved chains) ----
        float sc[8][4] = {};
        #pragma unroll
        for (int kc = 0; kc < 4; kc++) {
            #pragma unroll
            for (int j = 0; j < 4; j++) {
                uint32_t b_h[4], b_l[4];
                int bbyte = (j * 16 + ((lane >> 4) << 3) + (lane & 7)) * (AP * 2)
                          + kc * 32 + ((lane >> 3) & 1) * 16;
                ldmx4(b_h, uKh + bbyte);
                ldmx4(b_l, uKl + bbyte);
                mma16816(sc[2 * j],     aq_h[kc], b_h[0], b_h[1]);
                mma16816(sc[2 * j + 1], aq_h[kc], b_h[2], b_h[3]);
                mma16816(sc[2 * j],     aq_h[kc], b_l[0], b_l[1]);
                mma16816(sc[2 * j + 1], aq_h[kc], b_l[2], b_l[3]);
                mma16816(sc[2 * j],     aq_l[kc], b_h[0], b_h[1]);
                mma16816(sc[2 * j + 1], aq_l[kc], b_h[2], b_h[3]);
            }
        }

        // ---- scale + causal mask (diagonal block only) ----
        #pragma unroll
        for (int nt = 0; nt < 8; nt++) {
            #pragma unroll
            for (int i = 0; i < 4; i++) sc[nt][i] *= 0.125f;
        }
        if (kb == qb) {
            int r0l = wid * 16 + (lane >> 2);
            #pragma unroll
            for (int nt = 0; nt < 8; nt++) {
                int col = nt * 8 + (lane & 3) * 2;
                if (col > r0l)         sc[nt][0] = -1e30f;
                if (col + 1 > r0l)     sc[nt][1] = -1e30f;
                if (col > r0l + 8)     sc[nt][2] = -1e30f;
                if (col + 1 > r0l + 8) sc[nt][3] = -1e30f;
            }
        }

        // ---- online softmax ----
        float mx0 = -1e30f, mx1 = -1e30f;
        #pragma unroll
        for (int nt = 0; nt < 8; nt++) {
            mx0 = fmaxf(mx0, fmaxf(sc[nt][0], sc[nt][1]));
            mx1 = fmaxf(mx1, fmaxf(sc[nt][2], sc[nt][3]));
        }
        mx0 = fmaxf(mx0, __shfl_xor_sync(0xffffffffu, mx0, 1));
        mx0 = fmaxf(mx0, __shfl_xor_sync(0xffffffffu, mx0, 2));
        mx1 = fmaxf(mx1, __shfl_xor_sync(0xffffffffu, mx1, 1));
        mx1 = fmaxf(mx1, __shfl_xor_sync(0xffffffffu, mx1, 2));

        float mn0 = fmaxf(m0r, mx0), mn1 = fmaxf(m1r, mx1);
        float cr0 = __expf(m0r - mn0), cr1 = __expf(m1r - mn1);

        float sum0 = 0.0f, sum1 = 0.0f;
        #pragma unroll
        for (int nt = 0; nt < 8; nt++) {
            float p0 = __expf(sc[nt][0] - mn0);
            float p1 = __expf(sc[nt][1] - mn0);
            float p2 = __expf(sc[nt][2] - mn1);
            float p3 = __expf(sc[nt][3] - mn1);
            sc[nt][0] = p0; sc[nt][1] = p1; sc[nt][2] = p2; sc[nt][3] = p3;
            sum0 += p0 + p1;
            sum1 += p2 + p3;
        }
        sum0 += __shfl_xor_sync(0xffffffffu, sum0, 1);
        sum0 += __shfl_xor_sync(0xffffffffu, sum0, 2);
        sum1 += __shfl_xor_sync(0xffffffffu, sum1, 1);
        sum1 += __shfl_xor_sync(0xffffffffu, sum1, 2);

        l0 = l0 * cr0 + sum0;  m0r = mn0;
        l1 = l1 * cr1 + sum1;  m1r = mn1;

        #pragma unroll
        for (int nt = 0; nt < 8; nt++) {
            oAcc[nt][0] *= cr0; oAcc[nt][1] *= cr0;
            oAcc[nt][2] *= cr1; oAcc[nt][3] *= cr1;
        }

        // ---- O += P V (3-term, interleaved chains; V frags via ldmatrix.trans) ----
        #pragma unroll
        for (int kc = 0; kc < 4; kc++) {
            uint32_t pa_h[4], pa_l[4];
            pa_h[0] = pack_hi(sc[2 * kc][0],     sc[2 * kc][1]);
            pa_h[1] = pack_hi(sc[2 * kc][2],     sc[2 * kc][3]);
            pa_h[2] = pack_hi(sc[2 * kc + 1][0], sc[2 * kc + 1][1]);
            pa_h[3] = pack_hi(sc[2 * kc + 1][2], sc[2 * kc + 1][3]);
            pa_l[0] = pack_lo(sc[2 * kc][0],     sc[2 * kc][1]);
            pa_l[1] = pack_lo(sc[2 * kc][2],     sc[2 * kc][3]);
            pa_l[2] = pack_lo(sc[2 * kc + 1][0], sc[2 * kc + 1][1]);
            pa_l[3] = pack_lo(sc[2 * kc + 1][2], sc[2 * kc + 1][3]);
            #pragma unroll
            for (int j = 0; j < 4; j++) {
                uint32_t v_h[4], v_l[4];
                int key   = kc * 16 + ((lane >> 3) & 1) * 8 + (lane & 7);
                int hd    = j * 16 + (lane >> 4) * 8;
                int vbyte = key * (AP * 2) + hd * 2;
                ldmx4t(v_h, uVh + vbyte);
                ldmx4t(v_l, uVl + vbyte);
                mma16816(oAcc[2 * j],     pa_h, v_h[0], v_h[1]);
                mma16816(oAcc[2 * j + 1], pa_h, v_h[2], v_h[3]);
                mma16816(oAcc[2 * j],     pa_h, v_l[0], v_l[1]);
                mma16816(oAcc[2 * j + 1], pa_h, v_l[2], v_l[3]);
                mma16816(oAcc[2 * j],     pa_l, v_h[0], v_h[1]);
                mma16816(oAcc[2 * j + 1], pa_l, v_h[2], v_h[3]);
            }
        }
        __syncthreads();
    }

    // ---- finalize: ctx hi/lo bf16 [B,S,D] ----
    const float inv0 = 1.0f / l0, inv1 = 1.0f / l1;
    const int b = bh >> 4, h = bh & 15;
    const int r0 = qb * 64 + wid * 16 + (lane >> 2);
    const int r1 = r0 + 8;
    #pragma unroll
    for (int nt = 0; nt < 8; nt++) {
        int hd = nt * 8 + (lane & 3) * 2;
        float v0 = oAcc[nt][0] * inv0, v1 = oAcc[nt][1] * inv0;
        float v2 = oAcc[nt][2] * inv1, v3 = oAcc[nt][3] * inv1;
        size_t o0 = ((size_t)(b * S_ + r0)) * D_ + h * HD_ + hd;
        size_t o1 = ((size_t)(b * S_ + r1)) * D_ + h * HD_ + hd;
        *(unsigned*)&g_ctx_hi[o0] = pack_hi(v0, v1);
        *(unsigned*)&g_ctx_lo[o0] = pack_lo(v0, v1);
        *(unsigned*)&g_ctx_hi[o1] = pack_hi(v2, v3);
        *(unsigned*)&g_ctx_lo[o1] = pack_lo(v2, v3);
    }
}

// ---------------------------------------------------------------------------
// fp32 -> (bf16 hi, bf16 lo) split of x (writes device globals directly)
// ---------------------------------------------------------------------------
__global__ void split_x_kernel(const float4* __restrict__ src)
{
    int i = blockIdx.x * blockDim.x + threadIdx.x;
    if (i >= GM * GK / 4) return;
    float4 v = src[i];
    __nv_bfloat16 hx = __float2bfloat16(v.x), hy = __float2bfloat16(v.y);
    __nv_bfloat16 hz = __float2bfloat16(v.z), hw = __float2bfloat16(v.w);
    __nv_bfloat16 lx = __float2bfloat16(v.x - __bfloat162float(hx));
    __nv_bfloat16 ly = __float2bfloat16(v.y - __bfloat162float(hy));
    __nv_bfloat16 lz = __float2bfloat16(v.z - __bfloat162float(hz));
    __nv_bfloat16 lw = __float2bfloat16(v.w - __bfloat162float(hw));
    ((__nv_bfloat162*)g_x_hi)[i * 2]     = __nv_bfloat162(hx, hy);
    ((__nv_bfloat162*)g_x_hi)[i * 2 + 1] = __nv_bfloat162(hz, hw);
    ((__nv_bfloat162*)g_x_lo)[i * 2]     = __nv_bfloat162(lx, ly);
    ((__nv_bfloat162*)g_x_lo)[i * 2 + 1] = __nv_bfloat162(lz, lw);
}

// ---------------------------------------------------------------------------
// Batched: W [K,N] fp32 -> Wt [N,K] bf16 hi/lo for all 4 weights (blockIdx.z)
// ---------------------------------------------------------------------------
__global__ void transpose_split4_kernel(const float* __restrict__ W0,
                                        const float* __restrict__ W1,
                                        const float* __restrict__ W2,
                                        const float* __restrict__ W3)
{
    __shared__ float tile[32][33];
    const float* W;
    __nv_bfloat16 *hi, *lo;
    switch (blockIdx.z) {
        case 0:  W = W0; hi = g_wqt_hi; lo = g_wqt_lo; break;
        case 1:  W = W1; hi = g_wkt_hi; lo = g_wkt_lo; break;
        case 2:  W = W2; hi = g_wvt_hi; lo = g_wvt_lo; break;
        default: W = W3; hi = g_wot_hi; lo = g_wot_lo; break;
    }
    const int tx = threadIdx.x, ty = threadIdx.y;
    const int k0 = blockIdx.y * 32;
    const int n0 = blockIdx.x * 32;
    #pragma unroll
    for (int j = 0; j < 4; j++)
        tile[ty + j * 8][tx] = W[(size_t)(k0 + ty + j * 8) * GN + n0 + tx];
    __syncthreads();
    #pragma unroll
    for (int j = 0; j < 4; j++) {
        int n = n0 + ty + j * 8;
        int k = k0 + tx;
        float v = tile[tx][ty + j * 8];
        __nv_bfloat16 hv = __float2bfloat16(v);
        hi[(size_t)n * GK + k] = hv;
        lo[(size_t)n * GK + k] = __float2bfloat16(v - __bfloat162float(hv));
    }
}

// ---------------------------------------------------------------------------
extern "C" void kernel_launch(void* const* d_in, const int* in_sizes, int n_in,
                              void* d_out, int out_size)
{
    const float* x  = (const float*)d_in[0];
    const float* Wq = (const float*)d_in[1];
    const float* Wk = (const float*)d_in[2];
    const float* Wv = (const float*)d_in[3];
    const float* Wo = (const float*)d_in[4];
    const float* bo = (const float*)d_in[5];
    float*       out = (float*)d_out;

    cudaFuncSetAttribute(mma_gemm_kernel<0>,
                         cudaFuncAttributeMaxDynamicSharedMemorySize, SMEM_GEMM);
    cudaFuncSetAttribute(mma_gemm_kernel<1>,
                         cudaFuncAttributeMaxDynamicSharedMemorySize, SMEM_GEMM);
    cudaFuncSetAttribute(attn_mma_kernel,
                         cudaFuncAttributeMaxDynamicSharedMemorySize, SMEM_ATTN);

    // 1) prep: split x, transpose+split all 4 weights (batched)
    split_x_kernel<<<(GM * GK / 4 + 255) / 256, 256>>>((const float4*)x);
    transpose_split4_kernel<<<dim3(GN / 32, GK / 32, 4), dim3(32, 8)>>>(Wq, Wk, Wv, Wo);

    // 2) QKV projections (warp MMA, 2-stage cp.async, 2 CTAs/SM) -> bf16 hi/lo
    mma_gemm_kernel<0><<<dim3(GN / 128, GM / 128, 3), 256, SMEM_GEMM>>>(nullptr, nullptr);

    // 3) attention (warp MMA flash, cp.async, occ=2) -> ctx hi/lo [B,S,D]
    attn_mma_kernel<<<dim3(S_ / 64, B_ * H_), 128, SMEM_ATTN>>>();

    // 4) output projection + bias (warp MMA) -> fp32 out
    mma_gemm_kernel<1><<<dim3(GN / 128, GM / 128, 1), 256, SMEM_GEMM>>>(bo, out);
}

// round 10
// speedup vs baseline: 1.1100x; 1.0041x over previous
#include <cuda_runtime.h>
#include <cuda_bf16.h>
#include <cstdint>

// Problem dims
#define B_  2
#define S_  2048
#define D_  1024
#define H_  16
#define HD_ 64
#define GM  (B_ * S_)   // 4096
#define GN  D_          // 1024
#define GK  D_          // 1024

// ---------------------------------------------------------------------------
// Scratch (__device__ globals; allocation-free rule)
// ---------------------------------------------------------------------------
__device__ __nv_bfloat16 g_x_hi[GM * GK];
__device__ __nv_bfloat16 g_x_lo[GM * GK];
__device__ __nv_bfloat16 g_qh[B_ * H_ * S_ * HD_];   // [B,H,S,HD]
__device__ __nv_bfloat16 g_ql[B_ * H_ * S_ * HD_];
__device__ __nv_bfloat16 g_kh[B_ * H_ * S_ * HD_];
__device__ __nv_bfloat16 g_kl[B_ * H_ * S_ * HD_];
__device__ __nv_bfloat16 g_vh[B_ * H_ * S_ * HD_];
__device__ __nv_bfloat16 g_vl[B_ * H_ * S_ * HD_];
__device__ __nv_bfloat16 g_ctx_hi[GM * GK];          // [B,S,D]
__device__ __nv_bfloat16 g_ctx_lo[GM * GK];
// transposed weights [N, K] K-major
__device__ __nv_bfloat16 g_wqt_hi[GN * GK];
__device__ __nv_bfloat16 g_wqt_lo[GN * GK];
__device__ __nv_bfloat16 g_wkt_hi[GN * GK];
__device__ __nv_bfloat16 g_wkt_lo[GN * GK];
__device__ __nv_bfloat16 g_wvt_hi[GN * GK];
__device__ __nv_bfloat16 g_wvt_lo[GN * GK];
__device__ __nv_bfloat16 g_wot_hi[GN * GK];
__device__ __nv_bfloat16 g_wot_lo[GN * GK];

// ---------------------------------------------------------------------------
// Warp-MMA / async-copy primitives (sm_80+; valid for plain sm_103 target)
// ---------------------------------------------------------------------------
__device__ __forceinline__ uint32_t smem_u32(const void* p) {
    uint32_t a;
    asm("{ .reg .u64 t; cvta.to.shared.u64 t, %1; cvt.u32.u64 %0, t; }"
        : "=r"(a) : "l"(p));
    return a;
}

__device__ __forceinline__ void mma16816(float* c, const uint32_t* a,
                                         uint32_t b0, uint32_t b1) {
    asm volatile(
        "mma.sync.aligned.m16n8k16.row.col.f32.bf16.bf16.f32 "
        "{%0,%1,%2,%3}, {%4,%5,%6,%7}, {%8,%9}, {%0,%1,%2,%3};"
        : "+f"(c[0]), "+f"(c[1]), "+f"(c[2]), "+f"(c[3])
        : "r"(a[0]), "r"(a[1]), "r"(a[2]), "r"(a[3]), "r"(b0), "r"(b1));
}

__device__ __forceinline__ void ldmx4(uint32_t* r, uint32_t addr) {
    asm volatile("ldmatrix.sync.aligned.m8n8.x4.shared.b16 {%0,%1,%2,%3}, [%4];"
        : "=r"(r[0]), "=r"(r[1]), "=r"(r[2]), "=r"(r[3]) : "r"(addr));
}

__device__ __forceinline__ void ldmx4t(uint32_t* r, uint32_t addr) {
    asm volatile("ldmatrix.sync.aligned.m8n8.x4.trans.shared.b16 {%0,%1,%2,%3}, [%4];"
        : "=r"(r[0]), "=r"(r[1]), "=r"(r[2]), "=r"(r[3]) : "r"(addr));
}

__device__ __forceinline__ void cpa16(uint32_t s, const void* g) {
    asm volatile("cp.async.cg.shared.global [%0], [%1], 16;"
                 :: "r"(s), "l"(g) : "memory");
}
#define CP_COMMIT() asm volatile("cp.async.commit_group;" ::: "memory")
#define CP_WAIT(n)  asm volatile("cp.async.wait_group %0;" :: "n"(n) : "memory")

__device__ __forceinline__ unsigned pack_hi(float x, float y) {
    __nv_bfloat162 t = __floats2bfloat162_rn(x, y);
    return *reinterpret_cast<unsigned*>(&t);
}
__device__ __forceinline__ unsigned pack_lo(float x, float y) {
    float xr = x - __bfloat162float(__float2bfloat16(x));
    float yr = y - __bfloat162float(__float2bfloat16(y));
    __nv_bfloat162 t = __floats2bfloat162_rn(xr, yr);
    return *reinterpret_cast<unsigned*>(&t);
}

// ---------------------------------------------------------------------------
// GEMM: C[128,128] tile of A[M,K] @ B[N,K]^T, split-bf16 3-term, fp32 acc.
// 256 threads = 8 warps (2m x 4n); warp tile 64x32; KC=32; 2-stage cp.async.
// Term-major MMA issue: same-acc RAW distance = 8.
// ---------------------------------------------------------------------------
#define GP 40                 // smem pitch in bf16 (80 bytes)
#define GT (128 * GP * 2)     // one tile: 10240 bytes
#define GSTAGE (4 * GT)       // one stage (Ah,Al,Bh,Bl): 40960 bytes
#define SMEM_GEMM (2 * GSTAGE)

__device__ __forceinline__ void gemm_issue(uint32_t sb,
    const char* Ah, const char* Al, const char* Bh, const char* Bl,
    int m0, int n0, int c, int t)
{
    int lrow = t >> 1, lq = (t & 1) * 2;
    size_t goA = (size_t)(m0 + lrow) * (GK * 2) + (size_t)c * 64 + lq * 16;
    size_t goB = (size_t)(n0 + lrow) * (GK * 2) + (size_t)c * 64 + lq * 16;
    uint32_t soff = lrow * (GP * 2) + lq * 16;
    cpa16(sb + soff,               Ah + goA);
    cpa16(sb + soff + 16,          Ah + goA + 16);
    cpa16(sb + GT + soff,          Al + goA);
    cpa16(sb + GT + soff + 16,     Al + goA + 16);
    cpa16(sb + 2 * GT + soff,      Bh + goB);
    cpa16(sb + 2 * GT + soff + 16, Bh + goB + 16);
    cpa16(sb + 3 * GT + soff,      Bl + goB);
    cpa16(sb + 3 * GT + soff + 16, Bl + goB + 16);
}

template <int MODE>
__global__ __launch_bounds__(256, 2)
void mma_gemm_kernel(const float* __restrict__ bias, float* __restrict__ dout)
{
    extern __shared__ char smem[];
    const uint32_t sbase = smem_u32(smem);

    const __nv_bfloat16 *Ah, *Al, *Bh, *Bl;
    __nv_bfloat16 *OutH = nullptr, *OutL = nullptr;
    if (MODE == 0) {
        Ah = g_x_hi; Al = g_x_lo;
        if (blockIdx.z == 0)      { Bh = g_wqt_hi; Bl = g_wqt_lo; OutH = g_qh; OutL = g_ql; }
        else if (blockIdx.z == 1) { Bh = g_wkt_hi; Bl = g_wkt_lo; OutH = g_kh; OutL = g_kl; }
        else                      { Bh = g_wvt_hi; Bl = g_wvt_lo; OutH = g_vh; OutL = g_vl; }
    } else {
        Ah = g_ctx_hi; Al = g_ctx_lo; Bh = g_wot_hi; Bl = g_wot_lo;
    }

    const int m0   = blockIdx.y * 128;
    const int n0   = blockIdx.x * 128;
    const int t    = threadIdx.x;
    const int lane = t & 31;
    const int wid  = t >> 5;
    const int wm   = wid >> 2;     // 0..1
    const int wn   = wid & 3;      // 0..3

    float acc[4][4][4] = {};

    const int NC = GK / 32;
    gemm_issue(sbase, (const char*)Ah, (const char*)Al,
               (const char*)Bh, (const char*)Bl, m0, n0, 0, t);
    CP_COMMIT();

    for (int c = 0; c < NC; c++) {
        if (c + 1 < NC) {
            gemm_issue(sbase + ((c + 1) & 1) * GSTAGE,
                       (const char*)Ah, (const char*)Al,
                       (const char*)Bh, (const char*)Bl, m0, n0, c + 1, t);
            CP_COMMIT();
            CP_WAIT(1);
        } else {
            CP_WAIT(0);
        }
        __syncthreads();

        const uint32_t sb  = sbase + (c & 1) * GSTAGE;
        const uint32_t uAh = sb,          uAl = sb + GT;
        const uint32_t uBh = sb + 2 * GT, uBl = sb + 3 * GT;

        #pragma unroll
        for (int ks = 0; ks < 2; ks++) {
            uint32_t a_h[4][4], a_l[4][4];
            int abyte = (wm * 64 + (lane & 15)) * (GP * 2) + ks * 32 + (lane >> 4) * 16;
            #pragma unroll
            for (int mt = 0; mt < 4; mt++) {
                ldmx4(a_h[mt], uAh + abyte + mt * 16 * (GP * 2));
                ldmx4(a_l[mt], uAl + abyte + mt * 16 * (GP * 2));
            }
            uint32_t b_h[2][4], b_l[2][4];
            #pragma unroll
            for (int j = 0; j < 2; j++) {
                int bbyte = (wn * 32 + j * 16 + ((lane >> 4) << 3) + (lane & 7)) * (GP * 2)
                          + ks * 32 + ((lane >> 3) & 1) * 16;
                ldmx4(b_h[j], uBh + bbyte);
                ldmx4(b_l[j], uBl + bbyte);
            }
            // term hh: 16 MMAs, each acc touched once
            #pragma unroll
            for (int mt = 0; mt < 4; mt++)
                #pragma unroll
                for (int j = 0; j < 2; j++) {
                    mma16816(acc[mt][2 * j],     a_h[mt], b_h[j][0], b_h[j][1]);
                    mma16816(acc[mt][2 * j + 1], a_h[mt], b_h[j][2], b_h[j][3]);
                }
            // term hl
            #pragma unroll
            for (int mt = 0; mt < 4; mt++)
                #pragma unroll
                for (int j = 0; j < 2; j++) {
                    mma16816(acc[mt][2 * j],     a_h[mt], b_l[j][0], b_l[j][1]);
                    mma16816(acc[mt][2 * j + 1], a_h[mt], b_l[j][2], b_l[j][3]);
                }
            // term lh
            #pragma unroll
            for (int mt = 0; mt < 4; mt++)
                #pragma unroll
                for (int j = 0; j < 2; j++) {
                    mma16816(acc[mt][2 * j],     a_l[mt], b_h[j][0], b_h[j][1]);
                    mma16816(acc[mt][2 * j + 1], a_l[mt], b_h[j][2], b_h[j][3]);
                }
        }
        __syncthreads();
    }

    // Epilogue
    #pragma unroll
    for (int mt = 0; mt < 4; mt++) {
        int mA = m0 + wm * 64 + mt * 16 + (lane >> 2);
        int mB = mA + 8;
        #pragma unroll
        for (int nt = 0; nt < 4; nt++) {
            int n = n0 + wn * 32 + nt * 8 + (lane & 3) * 2;
            float c0 = acc[mt][nt][0], c1 = acc[mt][nt][1];
            float c2 = acc[mt][nt][2], c3 = acc[mt][nt][3];
            if (MODE == 0) {
                int h = n >> 6, hd = n & 63;
                {
                    int b = mA >> 11, s = mA & (S_ - 1);
                    size_t o = ((size_t)((b * H_ + h) * S_) + s) * HD_ + hd;
                    *(unsigned*)&OutH[o] = pack_hi(c0, c1);
                    *(unsigned*)&OutL[o] = pack_lo(c0, c1);
                }
                {
                    int b = mB >> 11, s = mB & (S_ - 1);
                    size_t o = ((size_t)((b * H_ + h) * S_) + s) * HD_ + hd;
                    *(unsigned*)&OutH[o] = pack_hi(c2, c3);
                    *(unsigned*)&OutL[o] = pack_lo(c2, c3);
                }
            } else {
                float b0 = bias[n], b1 = bias[n + 1];
                *(float2*)&dout[(size_t)mA * GN + n] = make_float2(c0 + b0, c1 + b1);
                *(float2*)&dout[(size_t)mB * GN + n] = make_float2(c2 + b0, c3 + b1);
            }
        }
    }
}

// ---------------------------------------------------------------------------
// Flash attention with warp MMA, causal, split-bf16 3-term, 2-stage cp.async.
// grid (S/64, B*H), 128 threads = 4 warps; warp owns 16 query rows.
// Term-major MMA issue: same-acc RAW distance = 8.
// ---------------------------------------------------------------------------
#define AP 72                 // smem pitch in bf16 (144 bytes)
#define AT (64 * AP * 2)      // one tile: 9216 bytes
#define ASTAGE (4 * AT)       // Kh,Kl,Vh,Vl: 36864 bytes
#define SMEM_ATTN (2 * ASTAGE)

__device__ __forceinline__ void attn_issue_kv(uint32_t sb,
    const __nv_bfloat16* Kh, const __nv_bfloat16* Kl,
    const __nv_bfloat16* Vh, const __nv_bfloat16* Vl, int kb, int t)
{
    const uint4* gkh = (const uint4*)(Kh + (size_t)kb * 64 * HD_);
    const uint4* gkl = (const uint4*)(Kl + (size_t)kb * 64 * HD_);
    const uint4* gvh = (const uint4*)(Vh + (size_t)kb * 64 * HD_);
    const uint4* gvl = (const uint4*)(Vl + (size_t)kb * 64 * HD_);
    #pragma unroll
    for (int p = 0; p < 4; p++) {
        int idx = t + p * 128;
        int row = idx >> 3, q = idx & 7;
        uint32_t soff = row * (AP * 2) + q * 16;
        cpa16(sb + soff,          gkh + idx);
        cpa16(sb + AT + soff,     gkl + idx);
        cpa16(sb + 2 * AT + soff, gvh + idx);
        cpa16(sb + 3 * AT + soff, gvl + idx);
    }
}

__global__ __launch_bounds__(128, 2)
void attn_mma_kernel()
{
    extern __shared__ char smem[];
    const uint32_t sbase = smem_u32(smem);

    // heaviest (largest qb) blocks launch first
    const int qb   = gridDim.x - 1 - blockIdx.x;
    const int bh   = blockIdx.y;
    const int t    = threadIdx.x;
    const int lane = t & 31;
    const int wid  = t >> 5;

    const size_t head_off = (size_t)bh * S_ * HD_;
    const __nv_bfloat16* Qh = g_qh + head_off + (size_t)qb * 64 * HD_;
    const __nv_bfloat16* Ql = g_ql + head_off + (size_t)qb * 64 * HD_;
    const __nv_bfloat16* Kh = g_kh + head_off;
    const __nv_bfloat16* Kl = g_kl + head_off;
    const __nv_bfloat16* Vh = g_vh + head_off;
    const __nv_bfloat16* Vl = g_vl + head_off;

    // ---- stage Q into stage-1 K buffers via cp.async (group 0) ----
    {
        uint32_t qsb = sbase + ASTAGE;
        #pragma unroll
        for (int p = 0; p < 4; p++) {
            int idx = t + p * 128;
            int row = idx >> 3, q = idx & 7;
            uint32_t soff = row * (AP * 2) + q * 16;
            cpa16(qsb + soff,      ((const uint4*)Qh) + idx);
            cpa16(qsb + AT + soff, ((const uint4*)Ql) + idx);
        }
        CP_COMMIT();
    }
    // ---- kb=0 K/V into stage 0 (group 1) ----
    attn_issue_kv(sbase, Kh, Kl, Vh, Vl, 0, t);
    CP_COMMIT();

    CP_WAIT(1);           // Q group done; kb0 may still be in flight
    __syncthreads();

    uint32_t aq_h[4][4], aq_l[4][4];
    {
        uint32_t uQh = sbase + ASTAGE, uQl = sbase + ASTAGE + AT;
        int qbyte = (wid * 16 + (lane & 15)) * (AP * 2) + (lane >> 4) * 16;
        #pragma unroll
        for (int kc = 0; kc < 4; kc++) {
            ldmx4(aq_h[kc], uQh + qbyte + kc * 32);
            ldmx4(aq_l[kc], uQl + qbyte + kc * 32);
        }
    }
    __syncthreads();      // all warps have Q frags; stage-1 reusable

    float oAcc[8][4] = {};
    float m0r = -1e30f, m1r = -1e30f;
    float l0 = 0.0f, l1 = 0.0f;

    for (int kb = 0; kb <= qb; kb++) {
        if (kb < qb) {
            attn_issue_kv(sbase + ((kb + 1) & 1) * ASTAGE, Kh, Kl, Vh, Vl, kb + 1, t);
            CP_COMMIT();
            CP_WAIT(1);
        } else {
            CP_WAIT(0);
        }
        __syncthreads();

        const uint32_t sb  = sbase + (kb & 1) * ASTAGE;
        const uint32_t uKh = sb,          uKl = sb + AT;
        const uint32_t uVh = sb + 2 * AT, uVl = sb + 3 * AT;

        // ---- S = Q K^T (3-term, term-major: acc distance 8) ----
        float sc[8][4] = {};
        #pragma unroll
        for (int kc = 0; kc < 4; kc++) {
            uint32_t b_h[4][4], b_l[4][4];
            #pragma unroll
            for (int j = 0; j < 4; j++) {
                int bbyte = (j * 16 + ((lane >> 4) << 3) + (lane & 7)) * (AP * 2)
                          + kc * 32 + ((lane >> 3) & 1) * 16;
                ldmx4(b_h[j], uKh + bbyte);
                ldmx4(b_l[j], uKl + bbyte);
            }
            #pragma unroll
            for (int j = 0; j < 4; j++) {
                mma16816(sc[2 * j],     aq_h[kc], b_h[j][0], b_h[j][1]);
                mma16816(sc[2 * j + 1], aq_h[kc], b_h[j][2], b_h[j][3]);
            }
            #pragma unroll
            for (int j = 0; j < 4; j++) {
                mma16816(sc[2 * j],     aq_h[kc], b_l[j][0], b_l[j][1]);
                mma16816(sc[2 * j + 1], aq_h[kc], b_l[j][2], b_l[j][3]);
            }
            #pragma unroll
            for (int j = 0; j < 4; j++) {
                mma16816(sc[2 * j],     aq_l[kc], b_h[j][0], b_h[j][1]);
                mma16816(sc[2 * j + 1], aq_l[kc], b_h[j][2], b_h[j][3]);
            }
        }

        // ---- scale + causal mask (diagonal block only) ----
        #pragma unroll
        for (int nt = 0; nt < 8; nt++) {
            #pragma unroll
            for (int i = 0; i < 4; i++) sc[nt][i] *= 0.125f;
        }
        if (kb == qb) {
            int r0l = wid * 16 + (lane >> 2);
            #pragma unroll
            for (int nt = 0; nt < 8; nt++) {
                int col = nt * 8 + (lane & 3) * 2;
                if (col > r0l)         sc[nt][0] = -1e30f;
                if (col + 1 > r0l)     sc[nt][1] = -1e30f;
                if (col > r0l + 8)     sc[nt][2] = -1e30f;
                if (col + 1 > r0l + 8) sc[nt][3] = -1e30f;
            }
        }

        // ---- online softmax ----
        float mx0 = -1e30f, mx1 = -1e30f;
        #pragma unroll
        for (int nt = 0; nt < 8; nt++) {
            mx0 = fmaxf(mx0, fmaxf(sc[nt][0], sc[nt][1]));
            mx1 = fmaxf(mx1, fmaxf(sc[nt][2], sc[nt][3]));
        }
        mx0 = fmaxf(mx0, __shfl_xor_sync(0xffffffffu, mx0, 1));
        mx0 = fmaxf(mx0, __shfl_xor_sync(0xffffffffu, mx0, 2));
        mx1 = fmaxf(mx1, __shfl_xor_sync(0xffffffffu, mx1, 1));
        mx1 = fmaxf(mx1, __shfl_xor_sync(0xffffffffu, mx1, 2));

        float mn0 = fmaxf(m0r, mx0), mn1 = fmaxf(m1r, mx1);
        float cr0 = __expf(m0r - mn0), cr1 = __expf(m1r - mn1);

        float sum0 = 0.0f, sum1 = 0.0f;
        #pragma unroll
        for (int nt = 0; nt < 8; nt++) {
            float p0 = __expf(sc[nt][0] - mn0);
            float p1 = __expf(sc[nt][1] - mn0);
            float p2 = __expf(sc[nt][2] - mn1);
            float p3 = __expf(sc[nt][3] - mn1);
            sc[nt][0] = p0; sc[nt][1] = p1; sc[nt][2] = p2; sc[nt][3] = p3;
            sum0 += p0 + p1;
            sum1 += p2 + p3;
        }
        sum0 += __shfl_xor_sync(0xffffffffu, sum0, 1);
        sum0 += __shfl_xor_sync(0xffffffffu, sum0, 2);
        sum1 += __shfl_xor_sync(0xffffffffu, sum1, 1);
        sum1 += __shfl_xor_sync(0xffffffffu, sum1, 2);

        l0 = l0 * cr0 + sum0;  m0r = mn0;
        l1 = l1 * cr1 + sum1;  m1r = mn1;

        #pragma unroll
        for (int nt = 0; nt < 8; nt++) {
            oAcc[nt][0] *= cr0; oAcc[nt][1] *= cr0;
            oAcc[nt][2] *= cr1; oAcc[nt][3] *= cr1;
        }

        // ---- O += P V (3-term, term-major: acc distance 8) ----
        #pragma unroll
        for (int kc = 0; kc < 4; kc++) {
            uint32_t pa_h[4], pa_l[4];
            pa_h[0] = pack_hi(sc[2 * kc][0],     sc[2 * kc][1]);
            pa_h[1] = pack_hi(sc[2 * kc][2],     sc[2 * kc][3]);
            pa_h[2] = pack_hi(sc[2 * kc + 1][0], sc[2 * kc + 1][1]);
            pa_h[3] = pack_hi(sc[2 * kc + 1][2], sc[2 * kc + 1][3]);
            pa_l[0] = pack_lo(sc[2 * kc][0],     sc[2 * kc][1]);
            pa_l[1] = pack_lo(sc[2 * kc][2],     sc[2 * kc][3]);
            pa_l[2] = pack_lo(sc[2 * kc + 1][0], sc[2 * kc + 1][1]);
            pa_l[3] = pack_lo(sc[2 * kc + 1][2], sc[2 * kc + 1][3]);
            uint32_t v_h[4][4], v_l[4][4];
            #pragma unroll
            for (int j = 0; j < 4; j++) {
                int key   = kc * 16 + ((lane >> 3) & 1) * 8 + (lane & 7);
                int hd    = j * 16 + (lane >> 4) * 8;
                int vbyte = key * (AP * 2) + hd * 2;
                ldmx4t(v_h[j], uVh + vbyte);
                ldmx4t(v_l[j], uVl + vbyte);
            }
            #pragma unroll
            for (int j = 0; j < 4; j++) {
                mma16816(oAcc[2 * j],     pa_h, v_h[j][0], v_h[j][1]);
                mma16816(oAcc[2 * j + 1], pa_h, v_h[j][2], v_h[j][3]);
            }
            #pragma unroll
            for (int j = 0; j < 4; j++) {
                mma16816(oAcc[2 * j],     pa_h, v_l[j][0], v_l[j][1]);
                mma16816(oAcc[2 * j + 1], pa_h, v_l[j][2], v_l[j][3]);
            }
            #pragma unroll
            for (int j = 0; j < 4; j++) {
                mma16816(oAcc[2 * j],     pa_l, v_h[j][0], v_h[j][1]);
                mma16816(oAcc[2 * j + 1], pa_l, v_h[j][2], v_h[j][3]);
            }
        }
        __syncthreads();
    }

    // ---- finalize: ctx hi/lo bf16 [B,S,D] ----
    const float inv0 = 1.0f / l0, inv1 = 1.0f / l1;
    const int b = bh >> 4, h = bh & 15;
    const int r0 = qb * 64 + wid * 16 + (lane >> 2);
    const int r1 = r0 + 8;
    #pragma unroll
    for (int nt = 0; nt < 8; nt++) {
        int hd = nt * 8 + (lane & 3) * 2;
        float v0 = oAcc[nt][0] * inv0, v1 = oAcc[nt][1] * inv0;
        float v2 = oAcc[nt][2] * inv1, v3 = oAcc[nt][3] * inv1;
        size_t o0 = ((size_t)(b * S_ + r0)) * D_ + h * HD_ + hd;
        size_t o1 = ((size_t)(b * S_ + r1)) * D_ + h * HD_ + hd;
        *(unsigned*)&g_ctx_hi[o0] = pack_hi(v0, v1);
        *(unsigned*)&g_ctx_lo[o0] = pack_lo(v0, v1);
        *(unsigned*)&g_ctx_hi[o1] = pack_hi(v2, v3);
        *(unsigned*)&g_ctx_lo[o1] = pack_lo(v2, v3);
    }
}

// ---------------------------------------------------------------------------
// fp32 -> (bf16 hi, bf16 lo) split of x (writes device globals directly)
// ---------------------------------------------------------------------------
__global__ void split_x_kernel(const float4* __restrict__ src)
{
    int i = blockIdx.x * blockDim.x + threadIdx.x;
    if (i >= GM * GK / 4) return;
    float4 v = src[i];
    __nv_bfloat16 hx = __float2bfloat16(v.x), hy = __float2bfloat16(v.y);
    __nv_bfloat16 hz = __float2bfloat16(v.z), hw = __float2bfloat16(v.w);
    __nv_bfloat16 lx = __float2bfloat16(v.x - __bfloat162float(hx));
    __nv_bfloat16 ly = __float2bfloat16(v.y - __bfloat162float(hy));
    __nv_bfloat16 lz = __float2bfloat16(v.z - __bfloat162float(hz));
    __nv_bfloat16 lw = __float2bfloat16(v.w - __bfloat162float(hw));
    ((__nv_bfloat162*)g_x_hi)[i * 2]     = __nv_bfloat162(hx, hy);
    ((__nv_bfloat162*)g_x_hi)[i * 2 + 1] = __nv_bfloat162(hz, hw);
    ((__nv_bfloat162*)g_x_lo)[i * 2]     = __nv_bfloat162(lx, ly);
    ((__nv_bfloat162*)g_x_lo)[i * 2 + 1] = __nv_bfloat162(lz, lw);
}

// ---------------------------------------------------------------------------
// Batched: W [K,N] fp32 -> Wt [N,K] bf16 hi/lo for all 4 weights (blockIdx.z)
// ---------------------------------------------------------------------------
__global__ void transpose_split4_kernel(const float* __restrict__ W0,
                                        const float* __restrict__ W1,
                                        const float* __restrict__ W2,
                                        const float* __restrict__ W3)
{
    __shared__ float tile[32][33];
    const float* W;
    __nv_bfloat16 *hi, *lo;
    switch (blockIdx.z) {
        case 0:  W = W0; hi = g_wqt_hi; lo = g_wqt_lo; break;
        case 1:  W = W1; hi = g_wkt_hi; lo = g_wkt_lo; break;
        case 2:  W = W2; hi = g_wvt_hi; lo = g_wvt_lo; break;
        default: W = W3; hi = g_wot_hi; lo = g_wot_lo; break;
    }
    const int tx = threadIdx.x, ty = threadIdx.y;
    const int k0 = blockIdx.y * 32;
    const int n0 = blockIdx.x * 32;
    #pragma unroll
    for (int j = 0; j < 4; j++)
        tile[ty + j * 8][tx] = W[(size_t)(k0 + ty + j * 8) * GN + n0 + tx];
    __syncthreads();
    #pragma unroll
    for (int j = 0; j < 4; j++) {
        int n = n0 + ty + j * 8;
        int k = k0 + tx;
        float v = tile[tx][ty + j * 8];
        __nv_bfloat16 hv = __float2bfloat16(v);
        hi[(size_t)n * GK + k] = hv;
        lo[(size_t)n * GK + k] = __float2bfloat16(v - __bfloat162float(hv));
    }
}

// ---------------------------------------------------------------------------
extern "C" void kernel_launch(void* const* d_in, const int* in_sizes, int n_in,
                              void* d_out, int out_size)
{
    const float* x  = (const float*)d_in[0];
    const float* Wq = (const float*)d_in[1];
    const float* Wk = (const float*)d_in[2];
    const float* Wv = (const float*)d_in[3];
    const float* Wo = (const float*)d_in[4];
    const float* bo = (const float*)d_in[5];
    float*       out = (float*)d_out;

    cudaFuncSetAttribute(mma_gemm_kernel<0>,
                         cudaFuncAttributeMaxDynamicSharedMemorySize, SMEM_GEMM);
    cudaFuncSetAttribute(mma_gemm_kernel<1>,
                         cudaFuncAttributeMaxDynamicSharedMemorySize, SMEM_GEMM);
    cudaFuncSetAttribute(attn_mma_kernel,
                         cudaFuncAttributeMaxDynamicSharedMemorySize, SMEM_ATTN);

    // 1) prep: split x, transpose+split all 4 weights (batched)
    split_x_kernel<<<(GM * GK / 4 + 255) / 256, 256>>>((const float4*)x);
    transpose_split4_kernel<<<dim3(GN / 32, GK / 32, 4), dim3(32, 8)>>>(Wq, Wk, Wv, Wo);

    // 2) QKV projections (warp MMA, 2-stage cp.async, 2 CTAs/SM) -> bf16 hi/lo
    mma_gemm_kernel<0><<<dim3(GN / 128, GM / 128, 3), 256, SMEM_GEMM>>>(nullptr, nullptr);

    // 3) attention (warp MMA flash, cp.async, occ=2, term-major) -> ctx hi/lo
    attn_mma_kernel<<<dim3(S_ / 64, B_ * H_), 128, SMEM_ATTN>>>();

    // 4) output projection + bias (warp MMA) -> fp32 out
    mma_gemm_kernel<1><<<dim3(GN / 128, GM / 128, 1), 256, SMEM_GEMM>>>(bo, out);
}